// round 15
// baseline (speedup 1.0000x reference)
#include <cuda_runtime.h>
#include <cuda_bf16.h>
#include <cstdint>

#define F_DIM   35
#define T_PAD   512
#define LOG2E   1.4426950408889634f
#define LN2     0.6931471805599453f
#define CDEAD   (-(1 << 28))
#define DRIFT_T 24          // per-lane drift; 2 pairs/lane -> 12/pair (= R9 slope)

__device__ float g_partials[1024];
__device__ int   g_count = 0;

__device__ __forceinline__ float ex2f(float x) {
    float r; asm("ex2.approx.ftz.f32 %0, %1;" : "=f"(r) : "f"(x)); return r;
}
__device__ __forceinline__ float lg2f(float x) {
    float r; asm("lg2.approx.ftz.f32 %0, %1;" : "=f"(r) : "f"(x)); return r;
}
__device__ __forceinline__ float pow2i(int e) {   // 2^e, e in [-127,127]; -127 -> +0
    return __uint_as_float((unsigned)(127 + e) << 23);
}

// 256 threads = 8 warps = 4 tasks/CTA, 2 warps per task (wavefront split):
//   role 0 (warp A): pairs 0..63   -- free-running producer
//   role 1 (warp B): pairs 64..127 -- consumes A's boundary via shared ring
// Linear-domain CTC, per-thread power-of-2 refs, NORM every 8 frames.
__global__ __launch_bounds__(256, 1) void sctc_wave_kernel(
    const float* __restrict__ logits,        // (B,T,F)
    const float* __restrict__ blank_logit,   // (1,)
    const int*   __restrict__ targets,       // (B,S,F)
    const int*   __restrict__ input_lengths, // (B,)
    const int*   __restrict__ target_lengths,// (B,)
    float* __restrict__ out,
    int B, int T, int S, int nTasks)
{
    __shared__ float4 P4[4][T_PAD];    // per-task {q0,q1,pb,pad}
    __shared__ float  ring[4][T_PAD];  // per-task boundary ao (A's pair 63)
    __shared__ int    rA[4][64];       // per-task, per-window: A lane-31 ref
    __shared__ int    cnt[4];          // per-task progress counter
    __shared__ float  AeF[4][128];
    __shared__ float  AoF[4][128];
    __shared__ int    RFw[4][2][32];

    const int tid   = threadIdx.x;
    const int lane  = tid & 31;
    const int ltask = tid >> 6;          // 0..3
    const int role  = (tid >> 5) & 1;    // 0 = A, 1 = B
    const int ttid  = tid & 63;
    int  task = blockIdx.x * 4 + ltask;
    bool live = (task < nTasks);
    if (!live) task = 0;
    const int b = task / F_DIM;
    const int f = task - b * F_DIM;

    const float ub = blank_logit[0] * LOG2E;
    float4* Pw = P4[ltask];
    float*  Rg = ring[ltask];
    const unsigned int caddr = (unsigned int)__cvta_generic_to_shared(&cnt[ltask]);

    // ---- linear 3-class softmax (64 threads per task) ----
    for (int t = ttid; t < T; t += 64) {
        float u  = logits[(b * T + t) * F_DIM + f] * LOG2E;
        float m  = fmaxf(fabsf(u), ub);
        float s0 = ex2f(-u - m);
        float s1 = ex2f( u - m);
        float s2 = ex2f(ub - m);
        float iv = 1.0f / (s0 + s1 + s2);
        Pw[t] = make_float4(s0 * iv, s1 * iv, s2 * iv, 0.0f);
    }
    if (ttid == 0) cnt[ltask] = 0;

    // ---- per-pair structure (2 pairs per lane) ----
    const int pbase = role * 64 + lane * 2;
    bool  lab0, lab1;
    float sk0, sk1;
    {
        const int base = b * S * F_DIM + f;
        int lm1 = (pbase >= 1 && pbase - 1 < S) ? targets[base + (pbase - 1) * F_DIM] : -1;
        int l0  = (pbase     < S) ? targets[base + (pbase    ) * F_DIM] : 0;
        int l1  = (pbase + 1 < S) ? targets[base + (pbase + 1) * F_DIM] : 0;
        lab0 = (l0 != 0); lab1 = (l1 != 0);
        sk0 = (pbase >= 1 && pbase     < S && l0 != lm1) ? 1.0f : 0.0f;
        sk1 = (              pbase + 1 < S && l1 != l0 ) ? 1.0f : 0.0f;
    }
    __syncthreads();

    // ---- init at t=0 ----
    float ae0 = 0.f, ae1 = 0.f, ao0 = 0.f, ao1 = 0.f;
    if (role == 0 && lane == 0) {
        float4 q = Pw[0];
        ae0 = q.z;
        ao0 = lab0 ? q.y : q.x;
    }
    int   R     = 0;
    float scIn  = 0.0f;
    float aoRaw = 0.0f;
    const bool lz = (lane == 0);

    const int Tin = input_lengths[b];
    const int nW  = (Tin - 1) >> 3;
    const int rem = (Tin - 1) & 7;

#define STEP_CORE(q4, T1EXPR, EXTRA)                                            \
    {                                                                           \
        float q0 = (q4).x, q1 = (q4).y, pbv = (q4).z;                           \
        float t1 = (T1EXPR);                                                    \
        float se0 = ae0 + t1;                                                   \
        float so0 = ao0 + ae0; so0 = __fmaf_rn(sk0, t1,  so0);                  \
        float se1 = ae1 + ao0;                                                  \
        float so1 = ao1 + ae1; so1 = __fmaf_rn(sk1, ao0, so1);                  \
        float pl1 = lab1 ? q1 : q0;                                             \
        float nao1 = so1 * pl1;                                                 \
        float aoN = __shfl_up_sync(0xffffffffu, nao1, 1);                       \
        float pl0 = lab0 ? q1 : q0;                                             \
        ae0 = se0 * pbv; ae1 = se1 * pbv;                                       \
        ao0 = so0 * pl0; ao1 = nao1;                                            \
        EXTRA;                                                                  \
        aoRaw = aoN;                                                            \
    }

    // Fresh-value normalize, 5-stage scan with DRIFT_T=24. seedC feeds lane 0
    // of warp B (cross-warp drift continuity); A passes CDEAD (no-op).
#define NORM(seedC)                                                             \
    {                                                                           \
        float mv = fmaxf(fmaxf(ae0, ao0), fmaxf(ae1, ao1));                     \
        int C = (mv > 0.0f)                                                     \
              ? (R + (int)((__float_as_uint(mv) >> 23) & 255u) - 127)           \
              : CDEAD;                                                          \
        if (lz) C = max(C, (seedC));                                            \
        _Pragma("unroll")                                                       \
        for (int o = 1; o < 32; o <<= 1) {                                      \
            int cu = __shfl_up_sync(0xffffffffu, C, o);                         \
            if (lane >= o) C = max(C, cu - DRIFT_T * (o));                      \
        }                                                                       \
        int Rn = C;                                                             \
        int Rp = __shfl_up_sync(0xffffffffu, Rn, 1);                            \
        if (lz) Rp = Rn - 200;                                                  \
        int d = Rp - Rn;                                                        \
        scIn = (d < -127) ? 0.0f : pow2i(min(d, 127));                          \
        int sh = R - Rn;                                                        \
        int sa = max(-127, min(127, sh));                                       \
        int sb = max(-127, min(127, sh - sa));                                  \
        float fa = pow2i(sa), fb = pow2i(sb);                                   \
        ae0 = (ae0*fa)*fb; ae1 = (ae1*fa)*fb;                                   \
        ao0 = (ao0*fa)*fb; ao1 = (ao1*fa)*fb;                                   \
        R = Rn;                                                                 \
        aoRaw = __shfl_up_sync(0xffffffffu, ao1, 1);                            \
    }

    if (role == 0) {
        // ================= warp A: free-running producer =================
        NORM(CDEAD);
        for (int W = 0; W < nW; ++W) {
            if (lane == 31) { rA[ltask][W] = R; Rg[8 * W] = ao1; }
            float4 q[8];
            #pragma unroll
            for (int j = 0; j < 8; ++j) q[j] = Pw[8 * W + 1 + j];
            int base = 8 * W + 1;
            #pragma unroll
            for (int j = 0; j < 8; ++j)
                STEP_CORE(q[j], aoRaw * scIn,
                          { if (lane == 31) Rg[base + j] = nao1; });
            if (lane == 31)
                asm volatile("st.release.cta.shared.b32 [%0], %1;"
                             :: "r"(caddr), "r"(W + 1) : "memory");
            NORM(CDEAD);
        }
        // tail (rem steps, refs already fresh from last NORM)
        if (lane == 31) { rA[ltask][nW] = R; Rg[8 * nW] = ao1; }
        int base = 8 * nW + 1;
        for (int j = 0; j < rem; ++j) {
            float4 q4 = Pw[base + j];
            STEP_CORE(q4, aoRaw * scIn,
                      { if (lane == 31) Rg[base + j] = nao1; });
        }
        if (lane == 31)
            asm volatile("st.release.cta.shared.b32 [%0], %1;"
                         :: "r"(caddr), "r"(nW + 1) : "memory");
    } else {
        // ================= warp B: lagging consumer =================
        for (int W = 0; W <= nW; ++W) {
            int target = W + 1;
            int v;
            do {
                asm volatile("ld.acquire.cta.shared.b32 %0, [%1];"
                             : "=r"(v) : "r"(caddr) : "memory");
            } while (v < target);
            int rAw = rA[ltask][W];
            NORM(rAw - DRIFT_T);
            int   dab = rAw - R;                 // <= DRIFT_T by the seed
            int   da1 = max(-127, min(127, dab));
            int   da2 = max(-127, min(127, dab - da1));
            float fab1 = pow2i(da1);
            float fab2 = pow2i(da2);
            int nst = (W < nW) ? 8 : rem;
            if (nst == 8) {
                float4 q[8]; float rg[8];
                #pragma unroll
                for (int j = 0; j < 8; ++j) { q[j] = Pw[8 * W + 1 + j]; rg[j] = Rg[8 * W + j]; }
                #pragma unroll
                for (int j = 0; j < 8; ++j)
                    STEP_CORE(q[j], lz ? (rg[j] * fab1) * fab2 : aoRaw * scIn, {});
            } else {
                for (int j = 0; j < nst; ++j) {
                    float4 q4 = Pw[8 * W + 1 + j];
                    float  rj = Rg[8 * W + j];
                    STEP_CORE(q4, lz ? (rj * fab1) * fab2 : aoRaw * scIn, {});
                }
            }
        }
    }

    // ---- spill finals ----
    AeF[ltask][pbase] = ae0; AeF[ltask][pbase + 1] = ae1;
    AoF[ltask][pbase] = ao0; AoF[ltask][pbase + 1] = ao1;
    RFw[ltask][role][lane] = R;
    __syncthreads();

    if (ttid == 0 && live) {
        int   Lt = target_lengths[b];
        int   p1 = Lt, p2 = Lt - 1;
        float v1 = AeF[ltask][p1]; int r1 = RFw[ltask][p1 >> 6][(p1 & 63) >> 1];
        float v2 = AoF[ltask][p2]; int r2 = RFw[ltask][p2 >> 6][(p2 & 63) >> 1];
        int   Rm = max(r1, r2);
        float w1 = (r1 - Rm < -127) ? 0.0f : pow2i(r1 - Rm);
        float w2 = (r2 - Rm < -127) ? 0.0f : pow2i(r2 - Rm);
        float v  = v1 * w1 + v2 * w2;
        float ll2  = lg2f(v) + (float)Rm;
        float loss = -ll2 * LN2;
        if (!(loss <= 0.5e30f)) loss = 0.0f;   // zero_infinity (also nan/inf)
        g_partials[task] = loss / (float)Lt;
    }
    __syncthreads();

    // ---- fused deterministic reduction (last CTA) ----
    bool isLast = false;
    if (tid == 0) {
        __threadfence();
        int old = atomicAdd(&g_count, 1);
        isLast = (old == (int)gridDim.x - 1);
    }
    if (tid < 32) {
        int last = __shfl_sync(0xffffffffu, isLast ? 1 : 0, 0);
        if (last) {
            float sv = 0.0f;
            for (int j = lane; j < nTasks; j += 32) sv += g_partials[j];
            #pragma unroll
            for (int o = 16; o; o >>= 1) sv += __shfl_down_sync(0xffffffffu, sv, o);
            if (lane == 0) {
                out[0] = sv / (float)nTasks;
                g_count = 0;               // reset for next graph replay
            }
        }
    }
#undef STEP_CORE
#undef NORM
}

extern "C" void kernel_launch(void* const* d_in, const int* in_sizes, int n_in,
                              void* d_out, int out_size)
{
    const float* logits  = (const float*)d_in[0];
    const float* blankl  = (const float*)d_in[1];
    const int*   targets = (const int*)d_in[2];
    const int*   in_len  = (const int*)d_in[3];
    const int*   tg_len  = (const int*)d_in[4];

    const int B = in_sizes[3];
    const int T = in_sizes[0] / (B * F_DIM);
    const int S = in_sizes[2] / (B * F_DIM);
    const int nTasks = B * F_DIM;
    const int nblk   = (nTasks + 3) / 4;

    sctc_wave_kernel<<<nblk, 256>>>(logits, blankl, targets, in_len, tg_len,
                                    (float*)d_out, B, T, S, nTasks);
}

// round 16
// speedup vs baseline: 1.2383x; 1.2383x over previous
#include <cuda_runtime.h>
#include <cuda_bf16.h>
#include <cstdint>

#define F_DIM   35
#define T_PAD   512
#define LOG2E   1.4426950408889634f
#define LN2     0.6931471805599453f
#define CDEAD   (-(1 << 28))
#define DRIFT_T 48

__device__ float g_partials[1024];
__device__ int   g_count = 0;

__device__ __forceinline__ float ex2f(float x) {
    float r; asm("ex2.approx.ftz.f32 %0, %1;" : "=f"(r) : "f"(x)); return r;
}
__device__ __forceinline__ float lg2f(float x) {
    float r; asm("lg2.approx.ftz.f32 %0, %1;" : "=f"(r) : "f"(x)); return r;
}
__device__ __forceinline__ float pow2i(int e) {   // 2^e, e in [-127,128]
    return __uint_as_float((unsigned)(127 + e) << 23);
}

// One WARP per (b,f) task; thread owns 4 state-pairs (R9 layout). Linear-domain
// CTC, per-thread power-of-2 refs, NORM every 8 frames with the EXACT
// prefix-max-with-drift scan — computed at radix 8 (serial depth 2 + Rp),
// bit-identical to the 5-stage version. Probs double-buffered: each 8-frame
// half-window's LDS.128s are issued before the NORM they hide under.
__global__ __launch_bounds__(128, 1) void sctc_warp_kernel(
    const float* __restrict__ logits,        // (B,T,F)
    const float* __restrict__ blank_logit,   // (1,)
    const int*   __restrict__ targets,       // (B,S,F)
    const int*   __restrict__ input_lengths, // (B,)
    const int*   __restrict__ target_lengths,// (B,)
    float* __restrict__ out,
    int B, int T, int S, int nTasks)
{
    __shared__ float4 P4[4][T_PAD];    // per-warp {q0, q1, pb, pad}
    __shared__ float  AeF[4][128];
    __shared__ float  AoF[4][128];
    __shared__ int    RF[4][32];

    const int tid  = threadIdx.x;
    const int lane = tid & 31;
    const int w    = tid >> 5;
    int  task = blockIdx.x * 4 + w;
    bool live = (task < nTasks);
    if (!live) task = 0;
    const int b = task / F_DIM;
    const int f = task - b * F_DIM;

    const float ub = blank_logit[0] * LOG2E;
    float4* Pw = P4[w];

    // ---- linear 3-class softmax, packed ----
    for (int t = lane; t < T; t += 32) {
        float u  = logits[(b * T + t) * F_DIM + f] * LOG2E;
        float m  = fmaxf(fabsf(u), ub);
        float s0 = ex2f(-u - m);
        float s1 = ex2f( u - m);
        float s2 = ex2f(ub - m);
        float iv = 1.0f / (s0 + s1 + s2);
        Pw[t] = make_float4(s0 * iv, s1 * iv, s2 * iv, 0.0f);
    }

    // ---- per-pair structure ----
    const int p0 = lane * 4;
    bool  labB[4];
    float skA[4];
    {
        const int base = b * S * F_DIM + f;
        int prev = (p0 >= 1 && p0 - 1 < S) ? targets[base + (p0 - 1) * F_DIM] : -1;
        #pragma unroll
        for (int i = 0; i < 4; ++i) {
            int p = p0 + i;
            int l = (p < S) ? targets[base + p * F_DIM] : 0;
            labB[i] = (l != 0);
            skA[i]  = (p >= 1 && p < S && l != prev) ? 1.0f : 0.0f;
            prev = l;
        }
    }
    __syncwarp();

    // ---- init at t=0 ----
    float ae0 = 0.f, ae1 = 0.f, ae2 = 0.f, ae3 = 0.f;
    float ao0 = 0.f, ao1 = 0.f, ao2 = 0.f, ao3 = 0.f;
    if (lane == 0) {
        float4 q = Pw[0];
        ae0 = q.z;
        ao0 = labB[0] ? q.y : q.x;
    }
    int   R     = 0;
    float scIn  = 0.0f;
    float aoRaw = 0.0f;   // raw shfl of neighbor's ao3 (lane0: scIn==0 kills it)
    const bool lz = (lane == 0);

    // One step, phase-batched (R9 verbatim).
#define STEP(q4)                                                                \
    {                                                                           \
        float q0 = (q4).x, q1 = (q4).y, pb = (q4).z;                            \
        float t1 = aoRaw * scIn;                                                \
        float se0 = ae0 + t1;                                                   \
        float se1 = ae1 + ao0;                                                  \
        float se2 = ae2 + ao1;                                                  \
        float se3 = ae3 + ao2;                                                  \
        float so0 = ao0 + ae0;                                                  \
        float so1 = ao1 + ae1;                                                  \
        float so2 = ao2 + ae2;                                                  \
        float so3 = ao3 + ae3;                                                  \
        so3 = __fmaf_rn(skA[3], ao2, so3);                                      \
        float pl3 = labB[3] ? q1 : q0;                                          \
        float nao3 = so3 * pl3;                                                 \
        float aoN = __shfl_up_sync(0xffffffffu, nao3, 1);                       \
        so0 = __fmaf_rn(skA[0], t1,  so0);                                      \
        so1 = __fmaf_rn(skA[1], ao0, so1);                                      \
        so2 = __fmaf_rn(skA[2], ao1, so2);                                      \
        float pl0 = labB[0] ? q1 : q0;                                          \
        float pl1 = labB[1] ? q1 : q0;                                          \
        float pl2 = labB[2] ? q1 : q0;                                          \
        ae0 = se0 * pb; ae1 = se1 * pb; ae2 = se2 * pb; ae3 = se3 * pb;         \
        ao0 = so0 * pl0; ao1 = so1 * pl1; ao2 = so2 * pl2; ao3 = nao3;          \
        aoRaw = aoN;                                                            \
    }

    // Fresh-value normalize; EXACT scan via radix 8 (bit-identical result to
    // the 5-stage version, serial shfl depth 2; Rp = one serial shfl).
#define NORM()                                                                  \
    {                                                                           \
        float mv = fmaxf(fmaxf(fmaxf(ae0, ao0), fmaxf(ae1, ao1)),               \
                         fmaxf(fmaxf(ae2, ao2), fmaxf(ae3, ao3)));              \
        int C = (mv > 0.0f)                                                     \
              ? (R + (int)((__float_as_uint(mv) >> 23) & 255u) - 127)           \
              : CDEAD;                                                          \
        int cu1 = __shfl_up_sync(0xffffffffu, C, 1);                            \
        int cu2 = __shfl_up_sync(0xffffffffu, C, 2);                            \
        int cu3 = __shfl_up_sync(0xffffffffu, C, 3);                            \
        int cu4 = __shfl_up_sync(0xffffffffu, C, 4);                            \
        int cu5 = __shfl_up_sync(0xffffffffu, C, 5);                            \
        int cu6 = __shfl_up_sync(0xffffffffu, C, 6);                            \
        int cu7 = __shfl_up_sync(0xffffffffu, C, 7);                            \
        int N = C;                                                              \
        if (lane >= 1) N = max(N, cu1 - 1 * DRIFT_T);                           \
        if (lane >= 2) N = max(N, cu2 - 2 * DRIFT_T);                           \
        if (lane >= 3) N = max(N, cu3 - 3 * DRIFT_T);                           \
        if (lane >= 4) N = max(N, cu4 - 4 * DRIFT_T);                           \
        if (lane >= 5) N = max(N, cu5 - 5 * DRIFT_T);                           \
        if (lane >= 6) N = max(N, cu6 - 6 * DRIFT_T);                           \
        if (lane >= 7) N = max(N, cu7 - 7 * DRIFT_T);                           \
        int nu8  = __shfl_up_sync(0xffffffffu, N, 8);                           \
        int nu16 = __shfl_up_sync(0xffffffffu, N, 16);                          \
        int nu24 = __shfl_up_sync(0xffffffffu, N, 24);                          \
        int Rn = N;                                                             \
        if (lane >= 8)  Rn = max(Rn, nu8  -  8 * DRIFT_T);                      \
        if (lane >= 16) Rn = max(Rn, nu16 - 16 * DRIFT_T);                      \
        if (lane >= 24) Rn = max(Rn, nu24 - 24 * DRIFT_T);                      \
        int Rp = __shfl_up_sync(0xffffffffu, Rn, 1);                            \
        if (lz) Rp = Rn - 200;                                                  \
        int d = Rp - Rn;                                                        \
        scIn = (d < -127) ? 0.0f : pow2i(min(d, 127));                          \
        int sh = R - Rn;                                                        \
        int sa = max(-127, min(127, sh));                                       \
        int sb = max(-127, min(127, sh - sa));                                  \
        float fa = pow2i(sa), fb = pow2i(sb);                                   \
        ae0 = (ae0*fa)*fb; ae1 = (ae1*fa)*fb; ae2 = (ae2*fa)*fb; ae3 = (ae3*fa)*fb; \
        ao0 = (ao0*fa)*fb; ao1 = (ao1*fa)*fb; ao2 = (ao2*fa)*fb; ao3 = (ao3*fa)*fb; \
        R = Rn;                                                                 \
        aoRaw = __shfl_up_sync(0xffffffffu, ao3, 1);                            \
    }

    NORM();   // initial (establishes scIn / aoRaw; runs on t=0 values)

    const int Tin = input_lengths[b];
    int t = 1;

    float4 qA[8], qB[8];
    // first half-window preload (exposed once)
    #pragma unroll
    for (int j = 0; j < 8; ++j) qA[j] = Pw[t + j];

    // Steady state: 16 frames/iter, NORM after each 8 (R9 cadence). Each
    // half's loads are issued BEFORE the NORM they drain under. Look-ahead
    // reads stay < T_PAD (max index Tin+7 <= 507).
    while (t + 16 <= Tin) {
        #pragma unroll
        for (int j = 0; j < 8; ++j) STEP(qA[j]);
        #pragma unroll
        for (int j = 0; j < 8; ++j) qB[j] = Pw[t + 8 + j];
        NORM();
        #pragma unroll
        for (int j = 0; j < 8; ++j) STEP(qB[j]);
        #pragma unroll
        for (int j = 0; j < 8; ++j) qA[j] = Pw[t + 16 + j];
        NORM();
        t += 16;
    }

    // Tail: r in [0,16). qA already holds P[t..t+7].
    {
        int r  = Tin - t;
        int n1 = (r < 8) ? r : 8;
        #pragma unroll
        for (int j = 0; j < 8; ++j) if (j < n1) STEP(qA[j]);
        if (r > 8) {
            NORM();
            #pragma unroll
            for (int j = 8; j < 16; ++j)
                if (j < r) { float4 q4 = Pw[t + j]; STEP(q4); }
        }
    }

    // ---- spill finals; lane 0 finalizes this task ----
    AeF[w][p0 + 0] = ae0; AeF[w][p0 + 1] = ae1; AeF[w][p0 + 2] = ae2; AeF[w][p0 + 3] = ae3;
    AoF[w][p0 + 0] = ao0; AoF[w][p0 + 1] = ao1; AoF[w][p0 + 2] = ao2; AoF[w][p0 + 3] = ao3;
    RF[w][lane] = R;
    __syncwarp();

    if (lane == 0 && live) {
        int   Lt = target_lengths[b];
        float v1 = AeF[w][Lt];     int r1 = RF[w][Lt >> 2];
        float v2 = AoF[w][Lt - 1]; int r2 = RF[w][(Lt - 1) >> 2];
        int   Rm = max(r1, r2);
        float w1 = (r1 - Rm < -127) ? 0.0f : pow2i(r1 - Rm);
        float w2 = (r2 - Rm < -127) ? 0.0f : pow2i(r2 - Rm);
        float v  = v1 * w1 + v2 * w2;
        float ll2  = lg2f(v) + (float)Rm;
        float loss = -ll2 * LN2;
        if (!(loss <= 0.5e30f)) loss = 0.0f;   // zero_infinity (also nan/inf)
        g_partials[task] = loss / (float)Lt;
    }
    __syncthreads();

    // ---- fused deterministic reduction (last CTA) ----
    bool isLast = false;
    if (tid == 0) {
        __threadfence();
        int old = atomicAdd(&g_count, 1);
        isLast = (old == (int)gridDim.x - 1);
    }
    if (tid < 32) {
        int last = __shfl_sync(0xffffffffu, isLast ? 1 : 0, 0);
        if (last) {
            float sv = 0.0f;
            for (int j = lane; j < nTasks; j += 32) sv += g_partials[j];
            #pragma unroll
            for (int o = 16; o; o >>= 1) sv += __shfl_down_sync(0xffffffffu, sv, o);
            if (lane == 0) {
                out[0] = sv / (float)nTasks;
                g_count = 0;               // reset for next graph replay
            }
        }
    }
#undef STEP
#undef NORM
}

extern "C" void kernel_launch(void* const* d_in, const int* in_sizes, int n_in,
                              void* d_out, int out_size)
{
    const float* logits  = (const float*)d_in[0];
    const float* blankl  = (const float*)d_in[1];
    const int*   targets = (const int*)d_in[2];
    const int*   in_len  = (const int*)d_in[3];
    const int*   tg_len  = (const int*)d_in[4];

    const int B = in_sizes[3];
    const int T = in_sizes[0] / (B * F_DIM);
    const int S = in_sizes[2] / (B * F_DIM);
    const int nTasks = B * F_DIM;
    const int nblk   = (nTasks + 3) / 4;

    sctc_warp_kernel<<<nblk, 128>>>(logits, blankl, targets, in_len, tg_len,
                                    (float*)d_out, B, T, S, nTasks);
}

// round 17
// speedup vs baseline: 1.4286x; 1.1537x over previous
#include <cuda_runtime.h>
#include <cuda_bf16.h>
#include <cstdint>

#define F_DIM   35
#define T_PAD   512
#define LOG2E   1.4426950408889634f
#define LN2     0.6931471805599453f
#define CDEAD   (-(1 << 28))
#define DRIFT_T 48

__device__ float g_partials[1024];
__device__ int   g_count = 0;

__device__ __forceinline__ float ex2f(float x) {
    float r; asm("ex2.approx.ftz.f32 %0, %1;" : "=f"(r) : "f"(x)); return r;
}
__device__ __forceinline__ float lg2f(float x) {
    float r; asm("lg2.approx.ftz.f32 %0, %1;" : "=f"(r) : "f"(x)); return r;
}
__device__ __forceinline__ float pow2i(int e) {   // 2^e, e in [-127,128]
    return __uint_as_float((unsigned)(127 + e) << 23);
}

// One WARP per (b,f) task; thread owns 4 state-pairs. Linear-domain CTC with
// the BLANK PROBABILITY FACTORED OUT: alpha~ = alpha / prod(pb). Even states
// update with a pure ADD (no multiply); odd states multiply by r = p_label/pb
// (exact exp ratios precomputed). The log2 of the blank product (SB) is summed
// in the preamble and re-added at finalize. NORM cadence/scan = R16 verbatim.
__global__ __launch_bounds__(128, 1) void sctc_warp_kernel(
    const float* __restrict__ logits,        // (B,T,F)
    const float* __restrict__ blank_logit,   // (1,)
    const int*   __restrict__ targets,       // (B,S,F)
    const int*   __restrict__ input_lengths, // (B,)
    const int*   __restrict__ target_lengths,// (B,)
    float* __restrict__ out,
    int B, int T, int S, int nTasks)
{
    __shared__ float2 P2[4][T_PAD];    // per-warp {r0 = p0/pb, r1 = p1/pb}
    __shared__ float  AeF[4][128];
    __shared__ float  AoF[4][128];
    __shared__ int    RF[4][32];

    const int tid  = threadIdx.x;
    const int lane = tid & 31;
    const int w    = tid >> 5;
    int  task = blockIdx.x * 4 + w;
    bool live = (task < nTasks);
    if (!live) task = 0;
    const int b = task / F_DIM;
    const int f = task - b * F_DIM;

    const float ub = blank_logit[0] * LOG2E;
    float2* Pw = P2[w];
    const int Tin = input_lengths[b];

    // ---- preamble: ratios r0,r1 into SMEM; SB = sum of lg2(pb) over t<Tin ----
    float sb = 0.0f;
    for (int t = lane; t < T; t += 32) {
        float u  = logits[(b * T + t) * F_DIM + f] * LOG2E;
        float m  = fmaxf(fabsf(u), ub);
        float s0 = ex2f(-u - m);
        float s1 = ex2f( u - m);
        float s2 = ex2f(ub - m);
        float lpb = (ub - m) - lg2f(s0 + s1 + s2);   // log2 p_blank
        if (t < Tin) sb += lpb;
        Pw[t] = make_float2(ex2f(-u - ub), ex2f(u - ub));  // exact ratios
    }
    #pragma unroll
    for (int o = 16; o; o >>= 1) sb += __shfl_xor_sync(0xffffffffu, sb, o);
    const float SB = sb;

    // ---- per-pair structure ----
    const int p0 = lane * 4;
    bool  labB[4];
    float skA[4];
    {
        const int base = b * S * F_DIM + f;
        int prev = (p0 >= 1 && p0 - 1 < S) ? targets[base + (p0 - 1) * F_DIM] : -1;
        #pragma unroll
        for (int i = 0; i < 4; ++i) {
            int p = p0 + i;
            int l = (p < S) ? targets[base + p * F_DIM] : 0;
            labB[i] = (l != 0);
            skA[i]  = (p >= 1 && p < S && l != prev) ? 1.0f : 0.0f;
            prev = l;
        }
    }
    __syncwarp();

    // ---- init at t=0 (tilde domain: ae = 1, ao = r_label) ----
    float ae0 = 0.f, ae1 = 0.f, ae2 = 0.f, ae3 = 0.f;
    float ao0 = 0.f, ao1 = 0.f, ao2 = 0.f, ao3 = 0.f;
    if (lane == 0) {
        float2 q = Pw[0];
        ae0 = 1.0f;
        ao0 = labB[0] ? q.y : q.x;
    }
    int   R     = 0;
    float scIn  = 0.0f;
    float aoRaw = 0.0f;
    const bool lz = (lane == 0);

    // One step, tilde domain: even = pure add; odd = add(+skip fma) * ratio.
#define STEP(q2)                                                                \
    {                                                                           \
        float r0 = (q2).x, r1 = (q2).y;                                         \
        float t1 = aoRaw * scIn;                                                \
        float so0 = ao0 + ae0;                                                  \
        float so1 = ao1 + ae1;                                                  \
        float so2 = ao2 + ae2;                                                  \
        float so3 = ao3 + ae3;                                                  \
        so3 = __fmaf_rn(skA[3], ao2, so3);                                      \
        float rl3 = labB[3] ? r1 : r0;                                          \
        float nao3 = so3 * rl3;                                                 \
        float aoN = __shfl_up_sync(0xffffffffu, nao3, 1);                       \
        so0 = __fmaf_rn(skA[0], t1,  so0);                                      \
        so1 = __fmaf_rn(skA[1], ao0, so1);                                      \
        so2 = __fmaf_rn(skA[2], ao1, so2);                                      \
        float rl0 = labB[0] ? r1 : r0;                                          \
        float rl1 = labB[1] ? r1 : r0;                                          \
        float rl2 = labB[2] ? r1 : r0;                                          \
        ae0 = ae0 + t1;                                                         \
        ae1 = ae1 + ao0;                                                        \
        ae2 = ae2 + ao1;                                                        \
        ae3 = ae3 + ao2;                                                        \
        ao0 = so0 * rl0; ao1 = so1 * rl1; ao2 = so2 * rl2; ao3 = nao3;          \
        aoRaw = aoN;                                                            \
    }

    // Fresh-value normalize; exact scan via radix 8 (R16 verbatim).
#define NORM()                                                                  \
    {                                                                           \
        float mv = fmaxf(fmaxf(fmaxf(ae0, ao0), fmaxf(ae1, ao1)),               \
                         fmaxf(fmaxf(ae2, ao2), fmaxf(ae3, ao3)));              \
        int C = (mv > 0.0f)                                                     \
              ? (R + (int)((__float_as_uint(mv) >> 23) & 255u) - 127)           \
              : CDEAD;                                                          \
        int cu1 = __shfl_up_sync(0xffffffffu, C, 1);                            \
        int cu2 = __shfl_up_sync(0xffffffffu, C, 2);                            \
        int cu3 = __shfl_up_sync(0xffffffffu, C, 3);                            \
        int cu4 = __shfl_up_sync(0xffffffffu, C, 4);                            \
        int cu5 = __shfl_up_sync(0xffffffffu, C, 5);                            \
        int cu6 = __shfl_up_sync(0xffffffffu, C, 6);                            \
        int cu7 = __shfl_up_sync(0xffffffffu, C, 7);                            \
        int N = C;                                                              \
        if (lane >= 1) N = max(N, cu1 - 1 * DRIFT_T);                           \
        if (lane >= 2) N = max(N, cu2 - 2 * DRIFT_T);                           \
        if (lane >= 3) N = max(N, cu3 - 3 * DRIFT_T);                           \
        if (lane >= 4) N = max(N, cu4 - 4 * DRIFT_T);                           \
        if (lane >= 5) N = max(N, cu5 - 5 * DRIFT_T);                           \
        if (lane >= 6) N = max(N, cu6 - 6 * DRIFT_T);                           \
        if (lane >= 7) N = max(N, cu7 - 7 * DRIFT_T);                           \
        int nu8  = __shfl_up_sync(0xffffffffu, N, 8);                           \
        int nu16 = __shfl_up_sync(0xffffffffu, N, 16);                          \
        int nu24 = __shfl_up_sync(0xffffffffu, N, 24);                          \
        int Rn = N;                                                             \
        if (lane >= 8)  Rn = max(Rn, nu8  -  8 * DRIFT_T);                      \
        if (lane >= 16) Rn = max(Rn, nu16 - 16 * DRIFT_T);                      \
        if (lane >= 24) Rn = max(Rn, nu24 - 24 * DRIFT_T);                      \
        int Rp = __shfl_up_sync(0xffffffffu, Rn, 1);                            \
        if (lz) Rp = Rn - 200;                                                  \
        int d = Rp - Rn;                                                        \
        scIn = (d < -127) ? 0.0f : pow2i(min(d, 127));                          \
        int sh = R - Rn;                                                        \
        int sa = max(-127, min(127, sh));                                       \
        int sb_ = max(-127, min(127, sh - sa));                                 \
        float fa = pow2i(sa), fb = pow2i(sb_);                                  \
        ae0 = (ae0*fa)*fb; ae1 = (ae1*fa)*fb; ae2 = (ae2*fa)*fb; ae3 = (ae3*fa)*fb; \
        ao0 = (ao0*fa)*fb; ao1 = (ao1*fa)*fb; ao2 = (ao2*fa)*fb; ao3 = (ao3*fa)*fb; \
        R = Rn;                                                                 \
        aoRaw = __shfl_up_sync(0xffffffffu, ao3, 1);                            \
    }

    NORM();   // initial (establishes scIn / aoRaw on t=0 values)

    int t = 1;
    float2 qA[8], qB[8];
    #pragma unroll
    for (int j = 0; j < 8; ++j) qA[j] = Pw[t + j];

    // Steady state: 16 frames/iter, NORM after each 8 (proven cadence). Each
    // half-window's LDS.64s are issued before the NORM they drain under.
    while (t + 16 <= Tin) {
        #pragma unroll
        for (int j = 0; j < 8; ++j) STEP(qA[j]);
        #pragma unroll
        for (int j = 0; j < 8; ++j) qB[j] = Pw[t + 8 + j];
        NORM();
        #pragma unroll
        for (int j = 0; j < 8; ++j) STEP(qB[j]);
        #pragma unroll
        for (int j = 0; j < 8; ++j) qA[j] = Pw[t + 16 + j];
        NORM();
        t += 16;
    }

    // Tail: r in [0,16). qA already holds P[t..t+7].
    {
        int r  = Tin - t;
        int n1 = (r < 8) ? r : 8;
        #pragma unroll
        for (int j = 0; j < 8; ++j) if (j < n1) STEP(qA[j]);
        if (r > 8) {
            NORM();
            #pragma unroll
            for (int j = 8; j < 16; ++j)
                if (j < r) { float2 q2 = Pw[t + j]; STEP(q2); }
        }
    }

    // ---- spill finals; lane 0 finalizes this task ----
    AeF[w][p0 + 0] = ae0; AeF[w][p0 + 1] = ae1; AeF[w][p0 + 2] = ae2; AeF[w][p0 + 3] = ae3;
    AoF[w][p0 + 0] = ao0; AoF[w][p0 + 1] = ao1; AoF[w][p0 + 2] = ao2; AoF[w][p0 + 3] = ao3;
    RF[w][lane] = R;
    __syncwarp();

    if (lane == 0 && live) {
        int   Lt = target_lengths[b];
        float v1 = AeF[w][Lt];     int r1 = RF[w][Lt >> 2];
        float v2 = AoF[w][Lt - 1]; int r2 = RF[w][(Lt - 1) >> 2];
        int   Rm = max(r1, r2);
        float w1 = (r1 - Rm < -127) ? 0.0f : pow2i(r1 - Rm);
        float w2 = (r2 - Rm < -127) ? 0.0f : pow2i(r2 - Rm);
        float v  = v1 * w1 + v2 * w2;
        float ll2  = lg2f(v) + (float)Rm + SB;   // re-apply blank product
        float loss = -ll2 * LN2;
        if (!(loss <= 0.5e30f)) loss = 0.0f;     // zero_infinity (also nan/inf)
        g_partials[task] = loss / (float)Lt;
    }
    __syncthreads();

    // ---- fused deterministic reduction (last CTA) ----
    bool isLast = false;
    if (tid == 0) {
        __threadfence();
        int old = atomicAdd(&g_count, 1);
        isLast = (old == (int)gridDim.x - 1);
    }
    if (tid < 32) {
        int last = __shfl_sync(0xffffffffu, isLast ? 1 : 0, 0);
        if (last) {
            float sv = 0.0f;
            for (int j = lane; j < nTasks; j += 32) sv += g_partials[j];
            #pragma unroll
            for (int o = 16; o; o >>= 1) sv += __shfl_down_sync(0xffffffffu, sv, o);
            if (lane == 0) {
                out[0] = sv / (float)nTasks;
                g_count = 0;               // reset for next graph replay
            }
        }
    }
#undef STEP
#undef NORM
}

extern "C" void kernel_launch(void* const* d_in, const int* in_sizes, int n_in,
                              void* d_out, int out_size)
{
    const float* logits  = (const float*)d_in[0];
    const float* blankl  = (const float*)d_in[1];
    const int*   targets = (const int*)d_in[2];
    const int*   in_len  = (const int*)d_in[3];
    const int*   tg_len  = (const int*)d_in[4];

    const int B = in_sizes[3];
    const int T = in_sizes[0] / (B * F_DIM);
    const int S = in_sizes[2] / (B * F_DIM);
    const int nTasks = B * F_DIM;
    const int nblk   = (nTasks + 3) / 4;

    sctc_warp_kernel<<<nblk, 128>>>(logits, blankl, targets, in_len, tg_len,
                                    (float*)d_out, B, T, S, nTasks);
}